// round 3
// baseline (speedup 1.0000x reference)
#include <cuda_runtime.h>

// ---------------------------------------------------------------------------
// Dual-EdgeConv (tpl/geo) + final MLP, fp32.
//   EdgeConv layer1 factorized:  pre1 = P[dst] + B[src],
//     P = x @ (W1a - W1b)^T + b1,  B = x @ W1b^T
//   BN1 folded into W2 ->  W2f, b2f
//   segment_max done on raw h2 via atomicMax (monotone uint encoding),
//   BN2 (monotone affine, g2 > 0) applied after aggregation.
// ---------------------------------------------------------------------------

static constexpr int NN   = 100000;
static constexpr int CIN  = 32;
static constexpr int HH   = 64;
static constexpr int COUT = 128;
static constexpr int EE   = 1000000;
static constexpr int MM   = EE + NN;          // virtual edges incl. self loops
#define GCU_EPS 1e-5f

// scratch (static device globals: no allocation in kernel_launch)
__device__ float    g_P[NN * HH];
__device__ float    g_B[NN * HH];
__device__ unsigned g_nodemax[NN * HH];
__device__ float    g_xcat[NN * COUT];
__device__ float    g_stats[4 * HH];    // [S1|SS1|S2|SS2]
__device__ float    g_fstats[2 * COUT]; // [Sf|SSf]
__device__ float    g_W2f[HH * HH];
__device__ float    g_b2f[HH];

// ---------------------------------------------------------------------------
__global__ __launch_bounds__(256) void k_init(int first) {
    int i  = blockIdx.x * blockDim.x + threadIdx.x;
    int st = gridDim.x * blockDim.x;
    for (int j = i; j < NN * HH; j += st) g_nodemax[j] = 0u;
    if (i < 4 * HH) g_stats[i] = 0.f;
    if (first && i < 2 * COUT) g_fstats[i] = 0.f;
}

// ---------------------------------------------------------------------------
// P[n][c] = sum_k x[n][k] * (W1[c][k] - W1[c][32+k])  + b1[c]
// B[n][c] = sum_k x[n][k] *  W1[c][32+k]
// one warp per node; weights staged k-major in smem (conflict-free).
__global__ __launch_bounds__(256) void k_precompute(const float* __restrict__ x,
                                                    const float* __restrict__ W1,
                                                    const float* __restrict__ b1) {
    __shared__ float Wp[CIN * HH];   // [k][c]
    __shared__ float Wb[CIN * HH];   // [k][c]
    __shared__ float b1s[HH];
    int t = threadIdx.x, lane = t & 31;
    for (int idx = t; idx < CIN * HH; idx += 256) {
        int c = idx >> 5, k = idx & 31;
        float wa = W1[c * 64 + k];
        float wb = W1[c * 64 + 32 + k];
        Wp[k * HH + c] = wa - wb;
        Wb[k * HH + c] = wb;
    }
    if (t < HH) b1s[t] = b1[t];
    __syncthreads();

    int gw = (blockIdx.x * 256 + t) >> 5;
    int nw = (gridDim.x * 256) >> 5;
    for (int n = gw; n < NN; n += nw) {
        float xv = x[n * CIN + lane];
        float ap  = b1s[lane], ap2 = b1s[lane + 32];
        float ab  = 0.f,       ab2 = 0.f;
#pragma unroll
        for (int k = 0; k < CIN; k++) {
            float xk = __shfl_sync(0xffffffffu, xv, k);
            ap  += xk * Wp[k * HH + lane];
            ap2 += xk * Wp[k * HH + 32 + lane];
            ab  += xk * Wb[k * HH + lane];
            ab2 += xk * Wb[k * HH + 32 + lane];
        }
        g_P[n * HH + lane]      = ap;
        g_P[n * HH + 32 + lane] = ap2;
        g_B[n * HH + lane]      = ab;
        g_B[n * HH + 32 + lane] = ab2;
    }
}

// ---------------------------------------------------------------------------
// BN1 stats over all MM virtual edges of h1 = relu(P[dst]+B[src]).
__global__ __launch_bounds__(256) void k_edge_stats(const int* __restrict__ src,
                                                    const int* __restrict__ dst) {
    __shared__ float red[2 * HH];
    int t = threadIdx.x, lane = t & 31;
    int gw = (blockIdx.x * 256 + t) >> 5;
    int nw = (gridDim.x * 256) >> 5;
    float s0 = 0.f, q0 = 0.f, s1 = 0.f, q1 = 0.f;
    for (int e = gw; e < MM; e += nw) {
        int sI, dI;
        if (e < EE) { sI = __ldg(&src[e]); dI = __ldg(&dst[e]); }
        else        { sI = dI = e - EE; }
        float h0 = fmaxf(__ldg(&g_P[dI * HH + lane])      + __ldg(&g_B[sI * HH + lane]),      0.f);
        float h1 = fmaxf(__ldg(&g_P[dI * HH + 32 + lane]) + __ldg(&g_B[sI * HH + 32 + lane]), 0.f);
        s0 += h0; q0 += h0 * h0;
        s1 += h1; q1 += h1 * h1;
    }
    if (t < 2 * HH) red[t] = 0.f;
    __syncthreads();
    atomicAdd(&red[lane], s0);
    atomicAdd(&red[lane + 32], s1);
    atomicAdd(&red[HH + lane], q0);
    atomicAdd(&red[HH + lane + 32], q1);
    __syncthreads();
    if (t < HH) {
        atomicAdd(&g_stats[t], red[t]);
        atomicAdd(&g_stats[HH + t], red[HH + t]);
    }
}

// ---------------------------------------------------------------------------
// Fold BN1 into layer-2 weights.
__global__ void k_fold(const float* __restrict__ W2, const float* __restrict__ b2,
                       const float* __restrict__ g1, const float* __restrict__ be1) {
    __shared__ float a[HH], dsh[HH];
    int t = threadIdx.x; // 64 threads
    float mu  = g_stats[t] * (1.f / (float)MM);
    float var = g_stats[HH + t] * (1.f / (float)MM) - mu * mu;
    float av  = g1[t] * rsqrtf(var + GCU_EPS);
    a[t]   = av;
    dsh[t] = be1[t] - mu * av;
    __syncthreads();
    float bb = b2[t];
#pragma unroll 8
    for (int c = 0; c < HH; c++) {
        float w = W2[t * HH + c];
        g_W2f[t * HH + c] = w * a[c];
        bb += w * dsh[c];
    }
    g_b2f[t] = bb;
}

// ---------------------------------------------------------------------------
// Layer-2 edge GEMM: tiles of 96 edges. Recompute h1, 64x64 matvec against
// W2f (smem), relu, BN2 stats, RED.MAX into g_nodemax.
static constexpr int TE = 96;           // edges per tile
static constexpr int HP = 68;           // padded smem row (floats, 16B aligned)

__global__ __launch_bounds__(256) void k_edge_gemm(const int* __restrict__ src,
                                                   const int* __restrict__ dst) {
    __shared__ __align__(16) float Wsh[HH * HP];
    __shared__ __align__(16) float h1s[TE * HP];
    __shared__ float b2s[HH];
    __shared__ int   dsts[TE];
    __shared__ float red[2 * HH];
    int t = threadIdx.x, lane = t & 31, w = t >> 5;

    for (int idx = t; idx < HH * HH; idx += 256) {
        int o = idx >> 6, c = idx & 63;
        Wsh[o * HP + c] = g_W2f[idx];
    }
    if (t < HH) b2s[t] = g_b2f[t];

    int eG = t >> 4;   // 0..15 -> edges eG*6 .. eG*6+5
    int oG = t & 15;   // 0..15 -> outputs oG + 16*j
    float ls[4] = {0.f, 0.f, 0.f, 0.f};
    float lq[4] = {0.f, 0.f, 0.f, 0.f};

    int NT = (MM + TE - 1) / TE;
    for (int tile = blockIdx.x; tile < NT; tile += gridDim.x) {
        __syncthreads();   // protect h1s vs previous phase2 (also covers W staging)
        // phase 1: 8 warps x 12 edges
        for (int i2 = 0; i2 < 12; i2++) {
            int el = w * 12 + i2;
            int eg = tile * TE + el;
            int sI = -1, dI = -1;
            if (eg < EE)      { sI = __ldg(&src[eg]); dI = __ldg(&dst[eg]); }
            else if (eg < MM) { sI = dI = eg - EE; }
            if (lane == 0) dsts[el] = dI;
            float h0 = 0.f, h1 = 0.f;
            if (dI >= 0) {
                h0 = fmaxf(__ldg(&g_P[dI * HH + lane])      + __ldg(&g_B[sI * HH + lane]),      0.f);
                h1 = fmaxf(__ldg(&g_P[dI * HH + 32 + lane]) + __ldg(&g_B[sI * HH + 32 + lane]), 0.f);
            }
            h1s[el * HP + lane]      = h0;
            h1s[el * HP + 32 + lane] = h1;
        }
        __syncthreads();
        // phase 2: 6 edges x 4 outputs per thread
        float acc[6][4];
#pragma unroll
        for (int i = 0; i < 6; i++)
#pragma unroll
            for (int j = 0; j < 4; j++) acc[i][j] = 0.f;

#pragma unroll
        for (int c4 = 0; c4 < HH; c4 += 4) {
            float4 wv[4];
#pragma unroll
            for (int j = 0; j < 4; j++)
                wv[j] = *(const float4*)&Wsh[(oG + 16 * j) * HP + c4];
#pragma unroll
            for (int i = 0; i < 6; i++) {
                float4 hv = *(const float4*)&h1s[(eG * 6 + i) * HP + c4];
#pragma unroll
                for (int j = 0; j < 4; j++) {
                    acc[i][j] += hv.x * wv[j].x + hv.y * wv[j].y
                               + hv.z * wv[j].z + hv.w * wv[j].w;
                }
            }
        }
        // epilogue: relu + stats + scatter-max
#pragma unroll
        for (int i = 0; i < 6; i++) {
            int d = dsts[eG * 6 + i];
            if (d < 0) continue;
#pragma unroll
            for (int j = 0; j < 4; j++) {
                int o = oG + 16 * j;
                float h2 = fmaxf(acc[i][j] + b2s[o], 0.f);
                ls[j] += h2;
                lq[j] += h2 * h2;
                atomicMax(&g_nodemax[(unsigned)d * HH + o],
                          __float_as_uint(h2) | 0x80000000u);
            }
        }
    }
    __syncthreads();
    if (t < 2 * HH) red[t] = 0.f;
    __syncthreads();
#pragma unroll
    for (int j = 0; j < 4; j++) {
        int o = oG + 16 * j;
        atomicAdd(&red[o], ls[j]);
        atomicAdd(&red[HH + o], lq[j]);
    }
    __syncthreads();
    if (t < HH) {
        atomicAdd(&g_stats[2 * HH + t], red[t]);
        atomicAdd(&g_stats[3 * HH + t], red[HH + t]);
    }
}

// ---------------------------------------------------------------------------
// Apply BN2 affine to aggregated max, write into concat buffer.
__global__ __launch_bounds__(256) void k_finalize(const float* __restrict__ g2,
                                                  const float* __restrict__ be2,
                                                  int off) {
    __shared__ float sc[HH], sh[HH];
    int t = threadIdx.x;
    if (t < HH) {
        float mu  = g_stats[2 * HH + t] * (1.f / (float)MM);
        float var = g_stats[3 * HH + t] * (1.f / (float)MM) - mu * mu;
        float inv = rsqrtf(var + GCU_EPS) * g2[t];
        sc[t] = inv;
        sh[t] = be2[t] - mu * inv;
    }
    __syncthreads();
    int i = blockIdx.x * 256 + t, st = gridDim.x * 256;
    for (; i < NN * HH; i += st) {
        int n = i >> 6, c = i & 63;
        float m = __uint_as_float(g_nodemax[i] & 0x7fffffffu);
        g_xcat[n * COUT + off + c] = m * sc[c] + sh[c];
    }
}

// ---------------------------------------------------------------------------
// Final MLP: h = relu(xcat @ Wf^T + bf), stats, h staged in d_out.
__global__ __launch_bounds__(256) void k_final_gemm(const float* __restrict__ Wf,
                                                    const float* __restrict__ bf,
                                                    float* __restrict__ out) {
    __shared__ float xs[128 * 33];
    __shared__ float Ws[128 * 33];
    __shared__ float bsh[COUT];
    __shared__ float red[2 * COUT];
    int t = threadIdx.x;
    int oG = t & 15;   // o = oG + 16*j
    int nG = t >> 4;   // n = nbase + nG + 16*i
    int nbase = blockIdx.x * 128;
    if (t < COUT) bsh[t] = bf[t];

    float acc[8][8];
#pragma unroll
    for (int i = 0; i < 8; i++)
#pragma unroll
        for (int j = 0; j < 8; j++) acc[i][j] = 0.f;

    for (int kt = 0; kt < 4; kt++) {
        __syncthreads();
        for (int idx = t; idx < 128 * 32; idx += 256) {
            int r = idx >> 5, k = idx & 31;
            int n = nbase + r;
            xs[r * 33 + k] = (n < NN) ? g_xcat[n * COUT + kt * 32 + k] : 0.f;
            Ws[r * 33 + k] = Wf[r * COUT + kt * 32 + k];
        }
        __syncthreads();
#pragma unroll
        for (int k = 0; k < 32; k++) {
            float xr[8], wr[8];
#pragma unroll
            for (int i = 0; i < 8; i++) xr[i] = xs[(nG + 16 * i) * 33 + k];
#pragma unroll
            for (int j = 0; j < 8; j++) wr[j] = Ws[(oG + 16 * j) * 33 + k];
#pragma unroll
            for (int i = 0; i < 8; i++)
#pragma unroll
                for (int j = 0; j < 8; j++) acc[i][j] += xr[i] * wr[j];
        }
    }

    float ls[8], lq[8];
#pragma unroll
    for (int j = 0; j < 8; j++) { ls[j] = 0.f; lq[j] = 0.f; }
#pragma unroll
    for (int i = 0; i < 8; i++) {
        int n = nbase + nG + 16 * i;
        if (n >= NN) continue;
#pragma unroll
        for (int j = 0; j < 8; j++) {
            int o = oG + 16 * j;
            float h = fmaxf(acc[i][j] + bsh[o], 0.f);
            out[n * COUT + o] = h;
            ls[j] += h;
            lq[j] += h * h;
        }
    }
    __syncthreads();
    if (t < 2 * COUT) red[t] = 0.f;
    __syncthreads();
#pragma unroll
    for (int j = 0; j < 8; j++) {
        int o = oG + 16 * j;
        atomicAdd(&red[o], ls[j]);
        atomicAdd(&red[COUT + o], lq[j]);
    }
    __syncthreads();
    if (t < COUT) {
        atomicAdd(&g_fstats[t], red[t]);
        atomicAdd(&g_fstats[COUT + t], red[COUT + t]);
    }
}

// ---------------------------------------------------------------------------
// Final BN, in place on d_out.
__global__ __launch_bounds__(256) void k_norm(const float* __restrict__ gf,
                                              const float* __restrict__ bef,
                                              float* __restrict__ out) {
    __shared__ float sc[COUT], sh[COUT];
    int t = threadIdx.x;
    if (t < COUT) {
        float mu  = g_fstats[t] * (1.f / (float)NN);
        float var = g_fstats[COUT + t] * (1.f / (float)NN) - mu * mu;
        float inv = rsqrtf(var + GCU_EPS) * gf[t];
        sc[t] = inv;
        sh[t] = bef[t] - mu * inv;
    }
    __syncthreads();
    int i = blockIdx.x * 256 + t, st = gridDim.x * 256;
    for (; i < NN * COUT; i += st) {
        int c = i & 127;
        out[i] = out[i] * sc[c] + sh[c];
    }
}

// ---------------------------------------------------------------------------
extern "C" void kernel_launch(void* const* d_in, const int* in_sizes, int n_in,
                              void* d_out, int out_size) {
    const float* x     = (const float*)d_in[0];
    const int*   tpl_e = (const int*)d_in[1];
    const int*   geo_e = (const int*)d_in[2];
    // per-conv params: W1, b1, g1, be1, W2, b2, g2, be2
    const float* prm[2][8];
    for (int c = 0; c < 2; c++)
        for (int k = 0; k < 8; k++)
            prm[c][k] = (const float*)d_in[3 + c * 8 + k];
    const float* mlp_W  = (const float*)d_in[19];
    const float* mlp_b  = (const float*)d_in[20];
    const float* mlp_g  = (const float*)d_in[21];
    const float* mlp_be = (const float*)d_in[22];
    float* out = (float*)d_out;

    for (int conv = 0; conv < 2; conv++) {
        const int* ei = conv ? geo_e : tpl_e;
        const float* W1  = prm[conv][0];
        const float* b1  = prm[conv][1];
        const float* g1  = prm[conv][2];
        const float* be1 = prm[conv][3];
        const float* W2  = prm[conv][4];
        const float* b2  = prm[conv][5];
        const float* g2  = prm[conv][6];
        const float* be2 = prm[conv][7];

        k_init<<<1024, 256>>>(conv == 0);
        k_precompute<<<1024, 256>>>(x, W1, b1);
        k_edge_stats<<<2048, 256>>>(ei, ei + EE);
        k_fold<<<1, 64>>>(W2, b2, g1, be1);
        k_edge_gemm<<<2072, 256>>>(ei, ei + EE);
        k_finalize<<<1024, 256>>>(g2, be2, conv * HH);
    }
    k_final_gemm<<<(NN + 127) / 128, 256>>>(mlp_W, mlp_b, out);
    k_norm<<<2048, 256>>>(mlp_g, mlp_be, out);
}

// round 7
// speedup vs baseline: 1.3971x; 1.3971x over previous
#include <cuda_runtime.h>
#include <cuda_bf16.h>
#include <cstdint>

// ---------------------------------------------------------------------------
// Dual-EdgeConv (tpl/geo) + final MLP, fp32 math, mma.sync (HMMA) edge GEMM.
//   layer1 factorized:  pre1 = P[dst] + B[src]
//   BN1 folded into W2 -> W2f, b2f
//   layer2 edge GEMM: bf16 double-split on tensor cores
//     h1 = hi+lo, W2f = Whi+Wlo;  h2 ~= hi*Whi + lo*Whi + hi*Wlo (err ~2^-18)
//   segment_max via LDG-filtered atomicMax (monotone uint encoding),
//   BN2 (monotone affine) applied after aggregation.
// ---------------------------------------------------------------------------

static constexpr int NN   = 100000;
static constexpr int CIN  = 32;
static constexpr int HH   = 64;
static constexpr int COUT = 128;
static constexpr int EE   = 1000000;
static constexpr int MM   = EE + NN;
#define GCU_EPS 1e-5f

__device__ float    g_P[NN * HH];
__device__ float    g_B[NN * HH];
__device__ unsigned g_nodemax[NN * HH];
__device__ float    g_xcat[NN * COUT];
__device__ float    g_stats[4 * HH];
__device__ float    g_fstats[2 * COUT];
__device__ float    g_W2f[HH * HH];
__device__ float    g_b2f[HH];

__device__ __forceinline__ uint32_t smem_u32(const void* p) {
    uint32_t a;
    asm("{ .reg .u64 t; cvta.to.shared.u64 t, %1; cvt.u32.u64 %0, t; }" : "=r"(a) : "l"(p));
    return a;
}
__device__ __forceinline__ void ldm_x4(uint32_t* r, uint32_t addr) {
    asm volatile("ldmatrix.sync.aligned.m8n8.x4.shared.b16 {%0,%1,%2,%3}, [%4];"
                 : "=r"(r[0]), "=r"(r[1]), "=r"(r[2]), "=r"(r[3]) : "r"(addr));
}
__device__ __forceinline__ void mma16816(float* c, const uint32_t* a, const uint32_t* b) {
    asm volatile("mma.sync.aligned.m16n8k16.row.col.f32.bf16.bf16.f32 "
                 "{%0,%1,%2,%3}, {%4,%5,%6,%7}, {%8,%9}, {%0,%1,%2,%3};"
                 : "+f"(c[0]), "+f"(c[1]), "+f"(c[2]), "+f"(c[3])
                 : "r"(a[0]), "r"(a[1]), "r"(a[2]), "r"(a[3]), "r"(b[0]), "r"(b[1]));
}

// ---------------------------------------------------------------------------
__global__ __launch_bounds__(256) void k_init(int first) {
    int i  = blockIdx.x * blockDim.x + threadIdx.x;
    int st = gridDim.x * blockDim.x;
    for (int j = i; j < NN * HH; j += st) g_nodemax[j] = 0u;
    if (i < 4 * HH) g_stats[i] = 0.f;
    if (first && i < 2 * COUT) g_fstats[i] = 0.f;
}

// ---------------------------------------------------------------------------
__global__ __launch_bounds__(256) void k_precompute(const float* __restrict__ x,
                                                    const float* __restrict__ W1,
                                                    const float* __restrict__ b1) {
    __shared__ float Wp[CIN * HH];
    __shared__ float Wb[CIN * HH];
    __shared__ float b1s[HH];
    int t = threadIdx.x, lane = t & 31;
    for (int idx = t; idx < CIN * HH; idx += 256) {
        int c = idx >> 5, k = idx & 31;
        float wa = W1[c * 64 + k];
        float wb = W1[c * 64 + 32 + k];
        Wp[k * HH + c] = wa - wb;
        Wb[k * HH + c] = wb;
    }
    if (t < HH) b1s[t] = b1[t];
    __syncthreads();

    int gw = (blockIdx.x * 256 + t) >> 5;
    int nw = (gridDim.x * 256) >> 5;
    for (int n = gw; n < NN; n += nw) {
        float xv = x[n * CIN + lane];
        float ap  = b1s[lane], ap2 = b1s[lane + 32];
        float ab  = 0.f,       ab2 = 0.f;
#pragma unroll
        for (int k = 0; k < CIN; k++) {
            float xk = __shfl_sync(0xffffffffu, xv, k);
            ap  += xk * Wp[k * HH + lane];
            ap2 += xk * Wp[k * HH + 32 + lane];
            ab  += xk * Wb[k * HH + lane];
            ab2 += xk * Wb[k * HH + 32 + lane];
        }
        g_P[n * HH + lane]      = ap;
        g_P[n * HH + 32 + lane] = ap2;
        g_B[n * HH + lane]      = ab;
        g_B[n * HH + 32 + lane] = ab2;
    }
}

// ---------------------------------------------------------------------------
__global__ __launch_bounds__(256) void k_edge_stats(const int* __restrict__ src,
                                                    const int* __restrict__ dst) {
    __shared__ float red[2 * HH];
    int t = threadIdx.x, lane = t & 31;
    int gw = (blockIdx.x * 256 + t) >> 5;
    int nw = (gridDim.x * 256) >> 5;
    float s0 = 0.f, q0 = 0.f, s1 = 0.f, q1 = 0.f;
    for (int e = gw; e < MM; e += nw) {
        int sI, dI;
        if (e < EE) { sI = __ldg(&src[e]); dI = __ldg(&dst[e]); }
        else        { sI = dI = e - EE; }
        float h0 = fmaxf(__ldg(&g_P[dI * HH + lane])      + __ldg(&g_B[sI * HH + lane]),      0.f);
        float h1 = fmaxf(__ldg(&g_P[dI * HH + 32 + lane]) + __ldg(&g_B[sI * HH + 32 + lane]), 0.f);
        s0 += h0; q0 += h0 * h0;
        s1 += h1; q1 += h1 * h1;
    }
    if (t < 2 * HH) red[t] = 0.f;
    __syncthreads();
    atomicAdd(&red[lane], s0);
    atomicAdd(&red[lane + 32], s1);
    atomicAdd(&red[HH + lane], q0);
    atomicAdd(&red[HH + lane + 32], q1);
    __syncthreads();
    if (t < HH) {
        atomicAdd(&g_stats[t], red[t]);
        atomicAdd(&g_stats[HH + t], red[HH + t]);
    }
}

// ---------------------------------------------------------------------------
__global__ void k_fold(const float* __restrict__ W2, const float* __restrict__ b2,
                       const float* __restrict__ g1, const float* __restrict__ be1) {
    __shared__ float a[HH], dsh[HH];
    int t = threadIdx.x; // 64 threads
    float mu  = g_stats[t] * (1.f / (float)MM);
    float var = g_stats[HH + t] * (1.f / (float)MM) - mu * mu;
    float av  = g1[t] * rsqrtf(var + GCU_EPS);
    a[t]   = av;
    dsh[t] = be1[t] - mu * av;
    __syncthreads();
    float bb = b2[t];
#pragma unroll 8
    for (int c = 0; c < HH; c++) {
        float w = W2[t * HH + c];
        g_W2f[t * HH + c] = w * a[c];
        bb += w * dsh[c];
    }
    g_b2f[t] = bb;
}

// ---------------------------------------------------------------------------
// Edge GEMM on mma.sync. Tile = 128 edges. 8 warps:
//   wrow = w&3 -> edge rows [wrow*32, +32), wcol = w>>2 -> channels [wcol*32, +32).
// A (smem): h1 hi/lo bf16, 128 rows x 64 cols (128B/row), 16B-column swizzle.
// Whi fragments in registers, Wlo fragments pre-arranged in smem.
// Epilogue: bias+relu, LDG-filtered atomicMax, BN2 stats in registers.
__global__ __launch_bounds__(256, 2) void k_edge_gemm_mma(const int* __restrict__ src,
                                                          const int* __restrict__ dst) {
    __shared__ __align__(16) unsigned char sAhi[128 * 128];
    __shared__ __align__(16) unsigned char sAlo[128 * 128];
    __shared__ __align__(16) uint32_t sWlo[2 * 4 * 4 * 32 * 2];   // [wcol][nb][kb][lane][2]
    __shared__ int dsts[128];

    int t = threadIdx.x, lane = t & 31, w = t >> 5;
    int wrow = w & 3, wcol = w >> 2;
    int g  = lane >> 2;      // 0..7
    int tg = lane & 3;       // 0..3

    // ---- build W fragments: Whi -> regs, Wlo -> smem ----
    uint32_t whi[4][4][2];
#pragma unroll
    for (int nb = 0; nb < 4; nb++) {
#pragma unroll
        for (int kb = 0; kb < 4; kb++) {
            int o  = wcol * 32 + nb * 8 + g;
            int k0 = kb * 16 + tg * 2;
            float w00 = g_W2f[o * 64 + k0],     w01 = g_W2f[o * 64 + k0 + 1];
            float w10 = g_W2f[o * 64 + k0 + 8], w11 = g_W2f[o * 64 + k0 + 9];
            __nv_bfloat162 h0 = __floats2bfloat162_rn(w00, w01);
            __nv_bfloat162 h1 = __floats2bfloat162_rn(w10, w11);
            float2 f0 = __bfloat1622float2(h0);
            float2 f1 = __bfloat1622float2(h1);
            __nv_bfloat162 l0 = __floats2bfloat162_rn(w00 - f0.x, w01 - f0.y);
            __nv_bfloat162 l1 = __floats2bfloat162_rn(w10 - f1.x, w11 - f1.y);
            whi[nb][kb][0] = *(uint32_t*)&h0;
            whi[nb][kb][1] = *(uint32_t*)&h1;
            if (wrow == 0) {
                int bidx = (((wcol * 4 + nb) * 4 + kb) * 32 + lane) * 2;
                sWlo[bidx]     = *(uint32_t*)&l0;
                sWlo[bidx + 1] = *(uint32_t*)&l1;
            }
        }
    }
    // bias per thread (8 channels)
    float b2r[8];
#pragma unroll
    for (int nb = 0; nb < 4; nb++) {
        b2r[nb * 2]     = g_b2f[wcol * 32 + nb * 8 + tg * 2];
        b2r[nb * 2 + 1] = g_b2f[wcol * 32 + nb * 8 + tg * 2 + 1];
    }

    // precompute ldmatrix addresses (fixed per thread)
    uint32_t aHiBase = smem_u32(sAhi), aLoBase = smem_u32(sAlo);
    int sub = lane >> 3, rr = lane & 7;
    uint32_t addrA[2][4];
#pragma unroll
    for (int mb = 0; mb < 2; mb++)
#pragma unroll
        for (int kb = 0; kb < 4; kb++) {
            int r    = wrow * 32 + mb * 16 + (sub & 1) * 8 + rr;
            int colb = kb * 32 + (sub >> 1) * 16;
            addrA[mb][kb] = (uint32_t)(r * 128 + (colb ^ ((r & 7) << 4)));
        }

    float sacc[8], qacc[8];
#pragma unroll
    for (int i = 0; i < 8; i++) { sacc[i] = 0.f; qacc[i] = 0.f; }

    int NTT = (MM + 127) >> 7;
    for (int tile = blockIdx.x; tile < NTT; tile += gridDim.x) {
        __syncthreads();   // dsts/A free (prev tile fully consumed)

        // ---- gather: warp w fills edge rows [w*16, w*16+16) ----
        int e0 = tile * 128 + w * 16;
        int sI = 0, dI = -1;
        if (lane < 16) {
            int mye = e0 + lane;
            if (mye < EE)      { sI = __ldg(&src[mye]); dI = __ldg(&dst[mye]); }
            else if (mye < MM) { sI = dI = mye - EE; }
            dsts[w * 16 + lane] = dI;
        }
#pragma unroll 4
        for (int e = 0; e < 16; e++) {
            int sE = __shfl_sync(0xffffffffu, sI, e);
            int dE = __shfl_sync(0xffffffffu, dI, e);
            int r  = w * 16 + e;
            float h0 = 0.f, h1 = 0.f;
            if (dE >= 0) {
                float2 p = *(const float2*)(g_P + (size_t)dE * HH + 2 * lane);
                float2 b = *(const float2*)(g_B + (size_t)sE * HH + 2 * lane);
                h0 = fmaxf(p.x + b.x, 0.f);
                h1 = fmaxf(p.y + b.y, 0.f);
            }
            __nv_bfloat162 hi2 = __floats2bfloat162_rn(h0, h1);
            float2 hf = __bfloat1622float2(hi2);
            __nv_bfloat162 lo2 = __floats2bfloat162_rn(h0 - hf.x, h1 - hf.y);
            int off = r * 128 + ((lane * 4) ^ ((r & 7) << 4));
            *(uint32_t*)(sAhi + off) = *(uint32_t*)&hi2;
            *(uint32_t*)(sAlo + off) = *(uint32_t*)&lo2;
        }
        __syncthreads();

        // ---- MMA: 2 m-blocks x 4 n-blocks x 4 k-blocks x 3 passes ----
        float acc[2][4][4];
#pragma unroll
        for (int mb = 0; mb < 2; mb++)
#pragma unroll
            for (int nb = 0; nb < 4; nb++)
#pragma unroll
                for (int j = 0; j < 4; j++) acc[mb][nb][j] = 0.f;

#pragma unroll
        for (int kb = 0; kb < 4; kb++) {
            uint32_t ahi[2][4], alo[2][4];
#pragma unroll
            for (int mb = 0; mb < 2; mb++) {
                ldm_x4(ahi[mb], aHiBase + addrA[mb][kb]);
                ldm_x4(alo[mb], aLoBase + addrA[mb][kb]);
            }
#pragma unroll
            for (int nb = 0; nb < 4; nb++) {
                uint2 wl = *(const uint2*)&sWlo[(((wcol * 4 + nb) * 4 + kb) * 32 + lane) * 2];
                uint32_t wlo[2] = { wl.x, wl.y };
#pragma unroll
                for (int mb = 0; mb < 2; mb++) {
                    mma16816(acc[mb][nb], ahi[mb], whi[nb][kb]);
                    mma16816(acc[mb][nb], alo[mb], whi[nb][kb]);
                    mma16816(acc[mb][nb], ahi[mb], wlo);
                }
            }
        }

        // ---- epilogue: bias+relu, stats, filtered atomicMax ----
#pragma unroll
        for (int mb = 0; mb < 2; mb++) {
#pragma unroll
            for (int half = 0; half < 2; half++) {
                int r = wrow * 32 + mb * 16 + g + half * 8;
                int d = dsts[r];
                if (d < 0) continue;
                unsigned* nm = g_nodemax + (size_t)d * HH + wcol * 32;
#pragma unroll
                for (int nb = 0; nb < 4; nb++) {
                    float v0 = fmaxf(acc[mb][nb][half * 2]     + b2r[nb * 2],     0.f);
                    float v1 = fmaxf(acc[mb][nb][half * 2 + 1] + b2r[nb * 2 + 1], 0.f);
                    sacc[nb * 2]     += v0; qacc[nb * 2]     += v0 * v0;
                    sacc[nb * 2 + 1] += v1; qacc[nb * 2 + 1] += v1 * v1;
                    int co = nb * 8 + tg * 2;
                    uint2 cur = __ldg((const uint2*)(nm + co));
                    unsigned e0v = __float_as_uint(v0) | 0x80000000u;
                    unsigned e1v = __float_as_uint(v1) | 0x80000000u;
                    if (e0v > cur.x) atomicMax(&nm[co], e0v);
                    if (e1v > cur.y) atomicMax(&nm[co + 1], e1v);
                }
            }
        }
    }

    // ---- BN2 stats reduction: lanes sharing tg hold same channels ----
#pragma unroll
    for (int i = 0; i < 8; i++) {
#pragma unroll
        for (int dlt = 16; dlt >= 4; dlt >>= 1) {
            sacc[i] += __shfl_down_sync(0xffffffffu, sacc[i], dlt);
            qacc[i] += __shfl_down_sync(0xffffffffu, qacc[i], dlt);
        }
    }
    if (lane < 4) {
#pragma unroll
        for (int nb = 0; nb < 4; nb++) {
            int o = wcol * 32 + nb * 8 + tg * 2;
            atomicAdd(&g_stats[2 * HH + o],     sacc[nb * 2]);
            atomicAdd(&g_stats[2 * HH + o + 1], sacc[nb * 2 + 1]);
            atomicAdd(&g_stats[3 * HH + o],     qacc[nb * 2]);
            atomicAdd(&g_stats[3 * HH + o + 1], qacc[nb * 2 + 1]);
        }
    }
}

// ---------------------------------------------------------------------------
__global__ __launch_bounds__(256) void k_finalize(const float* __restrict__ g2,
                                                  const float* __restrict__ be2,
                                                  int off) {
    __shared__ float sc[HH], sh[HH];
    int t = threadIdx.x;
    if (t < HH) {
        float mu  = g_stats[2 * HH + t] * (1.f / (float)MM);
        float var = g_stats[3 * HH + t] * (1.f / (float)MM) - mu * mu;
        float inv = rsqrtf(var + GCU_EPS) * g2[t];
        sc[t] = inv;
        sh[t] = be2[t] - mu * inv;
    }
    __syncthreads();
    int i = blockIdx.x * 256 + t, st = gridDim.x * 256;
    for (; i < NN * HH; i += st) {
        int c = i & 63;
        float m = __uint_as_float(g_nodemax[i] & 0x7fffffffu);
        g_xcat[(i >> 6) * COUT + off + c] = m * sc[c] + sh[c];
    }
}

// ---------------------------------------------------------------------------
__global__ __launch_bounds__(256) void k_final_gemm(const float* __restrict__ Wf,
                                                    const float* __restrict__ bf,
                                                    float* __restrict__ out) {
    __shared__ float xs[128 * 33];
    __shared__ float Ws[128 * 33];
    __shared__ float bsh[COUT];
    __shared__ float red[2 * COUT];
    int t = threadIdx.x;
    int oG = t & 15;
    int nG = t >> 4;
    int nbase = blockIdx.x * 128;
    if (t < COUT) bsh[t] = bf[t];

    float acc[8][8];
#pragma unroll
    for (int i = 0; i < 8; i++)
#pragma unroll
        for (int j = 0; j < 8; j++) acc[i][j] = 0.f;

    for (int kt = 0; kt < 4; kt++) {
        __syncthreads();
        for (int idx = t; idx < 128 * 32; idx += 256) {
            int r = idx >> 5, k = idx & 31;
            int n = nbase + r;
            xs[r * 33 + k] = (n < NN) ? g_xcat[n * COUT + kt * 32 + k] : 0.f;
            Ws[r * 33 + k] = Wf[r * COUT + kt * 32 + k];
        }
        __syncthreads();
#pragma unroll
        for (int k = 0; k < 32; k++) {
            float xr[8], wr[8];
#pragma unroll
            for (int i = 0; i < 8; i++) xr[i] = xs[(nG + 16 * i) * 33 + k];
#pragma unroll
            for (int j = 0; j < 8; j++) wr[j] = Ws[(oG + 16 * j) * 33 + k];
#pragma unroll
            for (int i = 0; i < 8; i++)
#pragma unroll
                for (int j = 0; j < 8; j++) acc[i][j] += xr[i] * wr[j];
        }
    }

    float ls[8], lq[8];
#pragma unroll
    for (int j = 0; j < 8; j++) { ls[j] = 0.f; lq[j] = 0.f; }
#pragma unroll
    for (int i = 0; i < 8; i++) {
        int n = nbase + nG + 16 * i;
        if (n >= NN) continue;
#pragma unroll
        for (int j = 0; j < 8; j++) {
            int o = oG + 16 * j;
            float h = fmaxf(acc[i][j] + bsh[o], 0.f);
            out[n * COUT + o] = h;
            ls[j] += h;
            lq[j] += h * h;
        }
    }
    __syncthreads();
    if (t < 2 * COUT) red[t] = 0.f;
    __syncthreads();
#pragma unroll
    for (int j = 0; j < 8; j++) {
        int o = oG + 16 * j;
        atomicAdd(&red[o], ls[j]);
        atomicAdd(&red[COUT + o], lq[j]);
    }
    __syncthreads();
    if (t < COUT) {
        atomicAdd(&g_fstats[t], red[t]);
        atomicAdd(&g_fstats[COUT + t], red[COUT + t]);
    }
}

// ---------------------------------------------------------------------------
__global__ __launch_bounds__(256) void k_norm(const float* __restrict__ gf,
                                              const float* __restrict__ bef,
                                              float* __restrict__ out) {
    __shared__ float sc[COUT], sh[COUT];
    int t = threadIdx.x;
    if (t < COUT) {
        float mu  = g_fstats[t] * (1.f / (float)NN);
        float var = g_fstats[COUT + t] * (1.f / (float)NN) - mu * mu;
        float inv = rsqrtf(var + GCU_EPS) * gf[t];
        sc[t] = inv;
        sh[t] = bef[t] - mu * inv;
    }
    __syncthreads();
    int i = blockIdx.x * 256 + t, st = gridDim.x * 256;
    for (; i < NN * COUT; i += st) {
        int c = i & 127;
        out[i] = out[i] * sc[c] + sh[c];
    }
}

// ---------------------------------------------------------------------------
extern "C" void kernel_launch(void* const* d_in, const int* in_sizes, int n_in,
                              void* d_out, int out_size) {
    const float* x     = (const float*)d_in[0];
    const int*   tpl_e = (const int*)d_in[1];
    const int*   geo_e = (const int*)d_in[2];
    const float* prm[2][8];
    for (int c = 0; c < 2; c++)
        for (int k = 0; k < 8; k++)
            prm[c][k] = (const float*)d_in[3 + c * 8 + k];
    const float* mlp_W  = (const float*)d_in[19];
    const float* mlp_b  = (const float*)d_in[20];
    const float* mlp_g  = (const float*)d_in[21];
    const float* mlp_be = (const float*)d_in[22];
    float* out = (float*)d_out;

    for (int conv = 0; conv < 2; conv++) {
        const int* ei = conv ? geo_e : tpl_e;
        k_init<<<1024, 256>>>(conv == 0);
        k_precompute<<<1024, 256>>>(x, prm[conv][0], prm[conv][1]);
        k_edge_stats<<<2048, 256>>>(ei, ei + EE);
        k_fold<<<1, 64>>>(prm[conv][4], prm[conv][5], prm[conv][2], prm[conv][3]);
        k_edge_gemm_mma<<<296, 256>>>(ei, ei + EE);
        k_finalize<<<1024, 256>>>(prm[conv][6], prm[conv][7], conv * HH);
    }
    k_final_gemm<<<(NN + 127) / 128, 256>>>(mlp_W, mlp_b, out);
    k_norm<<<2048, 256>>>(mlp_g, mlp_be, out);
}

// round 8
// speedup vs baseline: 1.4642x; 1.0480x over previous
#include <cuda_runtime.h>
#include <cuda_bf16.h>
#include <cstdint>

// ---------------------------------------------------------------------------
// Dual-EdgeConv (tpl/geo) + final MLP, fp32 math, mma.sync (HMMA) GEMMs.
//   layer1 factorized:  pre1 = P[dst] + B[src]
//   BN1 fold computed per-CTA inside the edge GEMM (no separate kernel)
//   layer2 edge GEMM + final MLP GEMM: bf16 double-split on tensor cores
//   segment_max via LDG-filtered atomicMax (monotone uint encoding,
//   nodemax initialized to enc(0) so zero/losing values skip the atomic),
//   BN2 (monotone affine) applied after aggregation.
// ---------------------------------------------------------------------------

static constexpr int NN   = 100000;
static constexpr int CIN  = 32;
static constexpr int HH   = 64;
static constexpr int COUT = 128;
static constexpr int EE   = 1000000;
static constexpr int MM   = EE + NN;
#define GCU_EPS 1e-5f

__device__ float    g_P[NN * HH];
__device__ float    g_B[NN * HH];
__device__ unsigned g_nodemax[NN * HH];
__device__ float    g_xcat[NN * COUT];
__device__ float    g_stats[4 * HH];
__device__ float    g_fstats[2 * COUT];

__device__ __forceinline__ uint32_t smem_u32(const void* p) {
    uint32_t a;
    asm("{ .reg .u64 t; cvta.to.shared.u64 t, %1; cvt.u32.u64 %0, t; }" : "=r"(a) : "l"(p));
    return a;
}
__device__ __forceinline__ void ldm_x4(uint32_t* r, uint32_t addr) {
    asm volatile("ldmatrix.sync.aligned.m8n8.x4.shared.b16 {%0,%1,%2,%3}, [%4];"
                 : "=r"(r[0]), "=r"(r[1]), "=r"(r[2]), "=r"(r[3]) : "r"(addr));
}
__device__ __forceinline__ void mma16816(float* c, const uint32_t* a, const uint32_t* b) {
    asm volatile("mma.sync.aligned.m16n8k16.row.col.f32.bf16.bf16.f32 "
                 "{%0,%1,%2,%3}, {%4,%5,%6,%7}, {%8,%9}, {%0,%1,%2,%3};"
                 : "+f"(c[0]), "+f"(c[1]), "+f"(c[2]), "+f"(c[3])
                 : "r"(a[0]), "r"(a[1]), "r"(a[2]), "r"(a[3]), "r"(b[0]), "r"(b[1]));
}
__device__ __forceinline__ void split2(float x, float y, uint32_t& hi, uint32_t& lo) {
    __nv_bfloat162 h2 = __floats2bfloat162_rn(x, y);
    float2 hf = __bfloat1622float2(h2);
    __nv_bfloat162 l2 = __floats2bfloat162_rn(x - hf.x, y - hf.y);
    hi = *(uint32_t*)&h2;
    lo = *(uint32_t*)&l2;
}

// ---------------------------------------------------------------------------
// Node precompute + all scratch clears (absorbs old k_init).
__global__ __launch_bounds__(256) void k_precompute(const float* __restrict__ x,
                                                    const float* __restrict__ W1,
                                                    const float* __restrict__ b1,
                                                    int first) {
    __shared__ float Wp[CIN * HH];
    __shared__ float Wb[CIN * HH];
    __shared__ float b1s[HH];
    int t = threadIdx.x, lane = t & 31;
    int gi = blockIdx.x * 256 + t, gst = gridDim.x * 256;
    for (int j = gi; j < NN * HH; j += gst) g_nodemax[j] = 0x80000000u;  // enc(0.0f)
    if (gi < 4 * HH) g_stats[gi] = 0.f;
    if (first && gi < 2 * COUT) g_fstats[gi] = 0.f;

    for (int idx = t; idx < CIN * HH; idx += 256) {
        int c = idx >> 5, k = idx & 31;
        float wa = W1[c * 64 + k];
        float wb = W1[c * 64 + 32 + k];
        Wp[k * HH + c] = wa - wb;
        Wb[k * HH + c] = wb;
    }
    if (t < HH) b1s[t] = b1[t];
    __syncthreads();

    int gw = gi >> 5;
    int nw = gst >> 5;
    for (int n = gw; n < NN; n += nw) {
        float xv = x[n * CIN + lane];
        float ap  = b1s[lane], ap2 = b1s[lane + 32];
        float ab  = 0.f,       ab2 = 0.f;
#pragma unroll
        for (int k = 0; k < CIN; k++) {
            float xk = __shfl_sync(0xffffffffu, xv, k);
            ap  += xk * Wp[k * HH + lane];
            ap2 += xk * Wp[k * HH + 32 + lane];
            ab  += xk * Wb[k * HH + lane];
            ab2 += xk * Wb[k * HH + 32 + lane];
        }
        g_P[n * HH + lane]      = ap;
        g_P[n * HH + 32 + lane] = ap2;
        g_B[n * HH + lane]      = ab;
        g_B[n * HH + 32 + lane] = ab2;
    }
}

// ---------------------------------------------------------------------------
__global__ __launch_bounds__(256) void k_edge_stats(const int* __restrict__ src,
                                                    const int* __restrict__ dst) {
    __shared__ float red[2 * HH];
    int t = threadIdx.x, lane = t & 31;
    int gw = (blockIdx.x * 256 + t) >> 5;
    int nw = (gridDim.x * 256) >> 5;
    float s0 = 0.f, q0 = 0.f, s1 = 0.f, q1 = 0.f;
    for (int e = gw; e < MM; e += nw) {
        int sI, dI;
        if (e < EE) { sI = __ldg(&src[e]); dI = __ldg(&dst[e]); }
        else        { sI = dI = e - EE; }
        float h0 = fmaxf(__ldg(&g_P[dI * HH + lane])      + __ldg(&g_B[sI * HH + lane]),      0.f);
        float h1 = fmaxf(__ldg(&g_P[dI * HH + 32 + lane]) + __ldg(&g_B[sI * HH + 32 + lane]), 0.f);
        s0 += h0; q0 += h0 * h0;
        s1 += h1; q1 += h1 * h1;
    }
    if (t < 2 * HH) red[t] = 0.f;
    __syncthreads();
    atomicAdd(&red[lane], s0);
    atomicAdd(&red[lane + 32], s1);
    atomicAdd(&red[HH + lane], q0);
    atomicAdd(&red[HH + lane + 32], q1);
    __syncthreads();
    if (t < HH) {
        atomicAdd(&g_stats[t], red[t]);
        atomicAdd(&g_stats[HH + t], red[HH + t]);
    }
}

// ---------------------------------------------------------------------------
// Edge GEMM on mma.sync, BN1 fold inlined per CTA.
// Tile = 128 edges. 8 warps: wrow=w&3 rows, wcol=w>>2 channel half.
__global__ __launch_bounds__(256, 2) void k_edge_gemm_mma(const int* __restrict__ src,
                                                          const int* __restrict__ dst,
                                                          const float* __restrict__ W2,
                                                          const float* __restrict__ b2,
                                                          const float* __restrict__ g1,
                                                          const float* __restrict__ be1) {
    __shared__ __align__(16) unsigned char sAhi[128 * 128];
    __shared__ __align__(16) unsigned char sAlo[128 * 128];
    __shared__ __align__(16) uint32_t sWlo[2 * 4 * 4 * 32 * 2];
    __shared__ float aS[HH], dS[HH];
    __shared__ int dsts[128];

    int t = threadIdx.x, lane = t & 31, w = t >> 5;
    int wrow = w & 3, wcol = w >> 2;
    int g  = lane >> 2;
    int tg = lane & 3;

    // ---- inline BN1 fold: a, dsh ----
    if (t < HH) {
        float mu  = g_stats[t] * (1.f / (float)MM);
        float var = g_stats[HH + t] * (1.f / (float)MM) - mu * mu;
        float av  = g1[t] * rsqrtf(var + GCU_EPS);
        aS[t] = av;
        dS[t] = be1[t] - mu * av;
    }
    __syncthreads();

    // ---- W fragments (folded): Whi regs, Wlo smem ----
    uint32_t whi[4][4][2];
#pragma unroll
    for (int nb = 0; nb < 4; nb++) {
#pragma unroll
        for (int kb = 0; kb < 4; kb++) {
            int o  = wcol * 32 + nb * 8 + g;
            int k0 = kb * 16 + tg * 2;
            float w00 = W2[o * 64 + k0]     * aS[k0];
            float w01 = W2[o * 64 + k0 + 1] * aS[k0 + 1];
            float w10 = W2[o * 64 + k0 + 8] * aS[k0 + 8];
            float w11 = W2[o * 64 + k0 + 9] * aS[k0 + 9];
            uint32_t h0, l0, h1, l1;
            split2(w00, w01, h0, l0);
            split2(w10, w11, h1, l1);
            whi[nb][kb][0] = h0;
            whi[nb][kb][1] = h1;
            if (wrow == 0) {
                int bidx = (((wcol * 4 + nb) * 4 + kb) * 32 + lane) * 2;
                sWlo[bidx]     = l0;
                sWlo[bidx + 1] = l1;
            }
        }
    }
    // folded bias b2f for this thread's 8 channels
    float b2r[8];
#pragma unroll
    for (int p = 0; p < 2; p++) {
        int o0 = wcol * 32 + tg * 2 + p;   // base; channels o0 + nb*8
        float bb[4];
#pragma unroll
        for (int nb = 0; nb < 4; nb++) bb[nb] = b2[o0 + nb * 8];
#pragma unroll 8
        for (int c = 0; c < HH; c++) {
            float dv = dS[c];
#pragma unroll
            for (int nb = 0; nb < 4; nb++) bb[nb] += W2[(o0 + nb * 8) * 64 + c] * dv;
        }
#pragma unroll
        for (int nb = 0; nb < 4; nb++) b2r[nb * 2 + p] = bb[nb];
    }

    uint32_t aHiBase = smem_u32(sAhi), aLoBase = smem_u32(sAlo);
    int sub = lane >> 3, rr = lane & 7;
    uint32_t addrA[2][4];
#pragma unroll
    for (int mb = 0; mb < 2; mb++)
#pragma unroll
        for (int kb = 0; kb < 4; kb++) {
            int r    = wrow * 32 + mb * 16 + (sub & 1) * 8 + rr;
            int colb = kb * 32 + (sub >> 1) * 16;
            addrA[mb][kb] = (uint32_t)(r * 128 + (colb ^ ((r & 7) << 4)));
        }

    float sacc[8], qacc[8];
#pragma unroll
    for (int i = 0; i < 8; i++) { sacc[i] = 0.f; qacc[i] = 0.f; }

    int NTT = (MM + 127) >> 7;
    for (int tile = blockIdx.x; tile < NTT; tile += gridDim.x) {
        __syncthreads();

        int e0 = tile * 128 + w * 16;
        int sI = 0, dI = -1;
        if (lane < 16) {
            int mye = e0 + lane;
            if (mye < EE)      { sI = __ldg(&src[mye]); dI = __ldg(&dst[mye]); }
            else if (mye < MM) { sI = dI = mye - EE; }
            dsts[w * 16 + lane] = dI;
        }
#pragma unroll 4
        for (int e = 0; e < 16; e++) {
            int sE = __shfl_sync(0xffffffffu, sI, e);
            int dE = __shfl_sync(0xffffffffu, dI, e);
            int r  = w * 16 + e;
            float h0 = 0.f, h1 = 0.f;
            if (dE >= 0) {
                float2 p = *(const float2*)(g_P + (size_t)dE * HH + 2 * lane);
                float2 b = *(const float2*)(g_B + (size_t)sE * HH + 2 * lane);
                h0 = fmaxf(p.x + b.x, 0.f);
                h1 = fmaxf(p.y + b.y, 0.f);
            }
            uint32_t hiw, low;
            split2(h0, h1, hiw, low);
            int off = r * 128 + ((lane * 4) ^ ((r & 7) << 4));
            *(uint32_t*)(sAhi + off) = hiw;
            *(uint32_t*)(sAlo + off) = low;
        }
        __syncthreads();

        float acc[2][4][4];
#pragma unroll
        for (int mb = 0; mb < 2; mb++)
#pragma unroll
            for (int nb = 0; nb < 4; nb++)
#pragma unroll
                for (int j = 0; j < 4; j++) acc[mb][nb][j] = 0.f;

#pragma unroll
        for (int kb = 0; kb < 4; kb++) {
            uint32_t ahi[2][4], alo[2][4];
#pragma unroll
            for (int mb = 0; mb < 2; mb++) {
                ldm_x4(ahi[mb], aHiBase + addrA[mb][kb]);
                ldm_x4(alo[mb], aLoBase + addrA[mb][kb]);
            }
#pragma unroll
            for (int nb = 0; nb < 4; nb++) {
                uint2 wl = *(const uint2*)&sWlo[(((wcol * 4 + nb) * 4 + kb) * 32 + lane) * 2];
                uint32_t wlo[2] = { wl.x, wl.y };
#pragma unroll
                for (int mb = 0; mb < 2; mb++) {
                    mma16816(acc[mb][nb], ahi[mb], whi[nb][kb]);
                    mma16816(acc[mb][nb], alo[mb], whi[nb][kb]);
                    mma16816(acc[mb][nb], ahi[mb], wlo);
                }
            }
        }

#pragma unroll
        for (int mb = 0; mb < 2; mb++) {
#pragma unroll
            for (int half = 0; half < 2; half++) {
                int r = wrow * 32 + mb * 16 + g + half * 8;
                int d = dsts[r];
                if (d < 0) continue;
                unsigned* nm = g_nodemax + (size_t)d * HH + wcol * 32;
#pragma unroll
                for (int nb = 0; nb < 4; nb++) {
                    float v0 = fmaxf(acc[mb][nb][half * 2]     + b2r[nb * 2],     0.f);
                    float v1 = fmaxf(acc[mb][nb][half * 2 + 1] + b2r[nb * 2 + 1], 0.f);
                    sacc[nb * 2]     += v0; qacc[nb * 2]     += v0 * v0;
                    sacc[nb * 2 + 1] += v1; qacc[nb * 2 + 1] += v1 * v1;
                    int co = nb * 8 + tg * 2;
                    uint2 cur = __ldg((const uint2*)(nm + co));
                    unsigned e0v = __float_as_uint(v0) | 0x80000000u;
                    unsigned e1v = __float_as_uint(v1) | 0x80000000u;
                    if (e0v > cur.x) atomicMax(&nm[co], e0v);
                    if (e1v > cur.y) atomicMax(&nm[co + 1], e1v);
                }
            }
        }
    }

#pragma unroll
    for (int i = 0; i < 8; i++) {
#pragma unroll
        for (int dlt = 16; dlt >= 4; dlt >>= 1) {
            sacc[i] += __shfl_down_sync(0xffffffffu, sacc[i], dlt);
            qacc[i] += __shfl_down_sync(0xffffffffu, qacc[i], dlt);
        }
    }
    if (lane < 4) {
#pragma unroll
        for (int nb = 0; nb < 4; nb++) {
            int o = wcol * 32 + nb * 8 + tg * 2;
            atomicAdd(&g_stats[2 * HH + o],     sacc[nb * 2]);
            atomicAdd(&g_stats[2 * HH + o + 1], sacc[nb * 2 + 1]);
            atomicAdd(&g_stats[3 * HH + o],     qacc[nb * 2]);
            atomicAdd(&g_stats[3 * HH + o + 1], qacc[nb * 2 + 1]);
        }
    }
}

// ---------------------------------------------------------------------------
__global__ __launch_bounds__(256) void k_finalize(const float* __restrict__ g2,
                                                  const float* __restrict__ be2,
                                                  int off) {
    __shared__ float sc[HH], sh[HH];
    int t = threadIdx.x;
    if (t < HH) {
        float mu  = g_stats[2 * HH + t] * (1.f / (float)MM);
        float var = g_stats[3 * HH + t] * (1.f / (float)MM) - mu * mu;
        float inv = rsqrtf(var + GCU_EPS) * g2[t];
        sc[t] = inv;
        sh[t] = be2[t] - mu * inv;
    }
    __syncthreads();
    int i = blockIdx.x * 256 + t, st = gridDim.x * 256;
    for (; i < NN * HH; i += st) {
        int c = i & 63;
        float m = __uint_as_float(g_nodemax[i] & 0x7fffffffu);
        g_xcat[(i >> 6) * COUT + off + c] = m * sc[c] + sh[c];
    }
}

// ---------------------------------------------------------------------------
// Final MLP GEMM on mma.sync: tile = 128 nodes x 128 out, K = 128, double-split.
// Dynamic smem: X hi/lo (2 x 32KB as 2 chunks of 64 cols) + W frags hi/lo (2 x 32KB).
static constexpr int FG_SMEM = 4 * 32768;

__global__ __launch_bounds__(256) void k_final_gemm_mma(const float* __restrict__ Wf,
                                                        const float* __restrict__ bf,
                                                        float* __restrict__ out) {
    extern __shared__ __align__(16) unsigned char sm[];
    unsigned char* sXhi = sm;                       // [chunk][128 rows][128B]
    unsigned char* sXlo = sm + 32768;
    uint32_t* sWhi = (uint32_t*)(sm + 65536);       // packed frags
    uint32_t* sWloF = (uint32_t*)(sm + 65536 + 32768);
    __shared__ float bsh[COUT];
    __shared__ float red[2 * COUT];

    int t = threadIdx.x, lane = t & 31, w = t >> 5;
    int wrow = w & 3, wcol = w >> 2;                // wcol in {0,1}: cols [wcol*64,+64)
    int g = lane >> 2, tg = lane & 3;

    if (t < COUT) bsh[t] = bf[t];
    red[t] = 0.f;
    red[t + 256 - 256] = red[t];                    // t covers 0..255 = 2*COUT

    // build W fragments: 128 sets (wcol2 x nb8 x kb8); warp w builds sets [w*16,+16)
    for (int i = 0; i < 16; i++) {
        int set  = w * 16 + i;
        int swc  = set >> 6, snb = (set >> 3) & 7, skb = set & 7;
        int o    = swc * 64 + snb * 8 + g;
        int k0   = skb * 16 + tg * 2;
        const float* Wr = Wf + o * COUT + k0;
        uint32_t h0, l0, h1, l1;
        split2(Wr[0], Wr[1], h0, l0);
        split2(Wr[8], Wr[9], h1, l1);
        int bidx = (((swc * 8 + snb) * 8 + skb) * 32 + lane) * 2;
        sWhi[bidx]      = h0;  sWhi[bidx + 1]  = h1;
        sWloF[bidx]     = l0;  sWloF[bidx + 1] = l1;
    }

    int nbase = blockIdx.x * 128;
    // stage X: 128 rows x 64 value-pairs (2 chunks x 32 pairs)
    for (int idx = t; idx < 128 * 64; idx += 256) {
        int r = idx >> 6, pp = idx & 63;
        int chunk = pp >> 5, p = pp & 31;
        int n = nbase + r;
        float2 v = (n < NN) ? *(const float2*)&g_xcat[n * COUT + chunk * 64 + 2 * p]
                            : make_float2(0.f, 0.f);
        uint32_t hiw, low;
        split2(v.x, v.y, hiw, low);
        int off = chunk * 16384 + r * 128 + ((p * 4) ^ ((r & 7) << 4));
        *(uint32_t*)(sXhi + off) = hiw;
        *(uint32_t*)(sXlo + off) = low;
    }
    __syncthreads();

    float acc[2][8][4];
#pragma unroll
    for (int mb = 0; mb < 2; mb++)
#pragma unroll
        for (int nb = 0; nb < 8; nb++)
#pragma unroll
            for (int j = 0; j < 4; j++) acc[mb][nb][j] = 0.f;

    uint32_t xHiBase = smem_u32(sXhi), xLoBase = smem_u32(sXlo);
    int sub = lane >> 3, rr = lane & 7;
#pragma unroll
    for (int kb = 0; kb < 8; kb++) {
        int chunk = kb >> 2, kk = kb & 3;
        uint32_t ahi[2][4], alo[2][4];
#pragma unroll
        for (int mb = 0; mb < 2; mb++) {
            int r    = wrow * 32 + mb * 16 + (sub & 1) * 8 + rr;
            int colb = kk * 32 + (sub >> 1) * 16;
            uint32_t a = (uint32_t)(chunk * 16384 + r * 128 + (colb ^ ((r & 7) << 4)));
            ldm_x4(ahi[mb], xHiBase + a);
            ldm_x4(alo[mb], xLoBase + a);
        }
#pragma unroll
        for (int nb = 0; nb < 8; nb++) {
            int bidx = (((wcol * 8 + nb) * 8 + kb) * 32 + lane) * 2;
            uint2 wh = *(const uint2*)&sWhi[bidx];
            uint2 wl = *(const uint2*)&sWloF[bidx];
            uint32_t whi2[2] = { wh.x, wh.y };
            uint32_t wlo2[2] = { wl.x, wl.y };
#pragma unroll
            for (int mb = 0; mb < 2; mb++) {
                mma16816(acc[mb][nb], ahi[mb], whi2);
                mma16816(acc[mb][nb], alo[mb], whi2);
                mma16816(acc[mb][nb], ahi[mb], wlo2);
            }
        }
    }

    // epilogue: bias+relu, write, stats
    float ls[16], lq[16];
#pragma unroll
    for (int i = 0; i < 16; i++) { ls[i] = 0.f; lq[i] = 0.f; }
#pragma unroll
    for (int mb = 0; mb < 2; mb++) {
#pragma unroll
        for (int half = 0; half < 2; half++) {
            int n = nbase + wrow * 32 + mb * 16 + half * 8 + g;
            if (n >= NN) continue;
#pragma unroll
            for (int nb = 0; nb < 8; nb++) {
                int o = wcol * 64 + nb * 8 + tg * 2;
                float v0 = fmaxf(acc[mb][nb][half * 2]     + bsh[o],     0.f);
                float v1 = fmaxf(acc[mb][nb][half * 2 + 1] + bsh[o + 1], 0.f);
                out[n * COUT + o]     = v0;
                out[n * COUT + o + 1] = v1;
                ls[nb * 2]     += v0; lq[nb * 2]     += v0 * v0;
                ls[nb * 2 + 1] += v1; lq[nb * 2 + 1] += v1 * v1;
            }
        }
    }
#pragma unroll
    for (int i = 0; i < 16; i++) {
#pragma unroll
        for (int dlt = 16; dlt >= 4; dlt >>= 1) {
            ls[i] += __shfl_down_sync(0xffffffffu, ls[i], dlt);
            lq[i] += __shfl_down_sync(0xffffffffu, lq[i], dlt);
        }
    }
    if (lane < 4) {
#pragma unroll
        for (int nb = 0; nb < 8; nb++) {
            int o = wcol * 64 + nb * 8 + tg * 2;
            atomicAdd(&red[o],            ls[nb * 2]);
            atomicAdd(&red[o + 1],        ls[nb * 2 + 1]);
            atomicAdd(&red[COUT + o],     lq[nb * 2]);
            atomicAdd(&red[COUT + o + 1], lq[nb * 2 + 1]);
        }
    }
    __syncthreads();
    if (t < COUT) {
        atomicAdd(&g_fstats[t],        red[t]);
        atomicAdd(&g_fstats[COUT + t], red[COUT + t]);
    }
}

// ---------------------------------------------------------------------------
__global__ __launch_bounds__(256) void k_norm(const float* __restrict__ gf,
                                              const float* __restrict__ bef,
                                              float* __restrict__ out) {
    __shared__ float sc[COUT], sh[COUT];
    int t = threadIdx.x;
    if (t < COUT) {
        float mu  = g_fstats[t] * (1.f / (float)NN);
        float var = g_fstats[COUT + t] * (1.f / (float)NN) - mu * mu;
        float inv = rsqrtf(var + GCU_EPS) * gf[t];
        sc[t] = inv;
        sh[t] = bef[t] - mu * inv;
    }
    __syncthreads();
    int i = blockIdx.x * 256 + t, st = gridDim.x * 256;
    for (; i < NN * COUT; i += st) {
        int c = i & 127;
        out[i] = out[i] * sc[c] + sh[c];
    }
}

// ---------------------------------------------------------------------------
extern "C" void kernel_launch(void* const* d_in, const int* in_sizes, int n_in,
                              void* d_out, int out_size) {
    const float* x     = (const float*)d_in[0];
    const int*   tpl_e = (const int*)d_in[1];
    const int*   geo_e = (const int*)d_in[2];
    const float* prm[2][8];
    for (int c = 0; c < 2; c++)
        for (int k = 0; k < 8; k++)
            prm[c][k] = (const float*)d_in[3 + c * 8 + k];
    const float* mlp_W  = (const float*)d_in[19];
    const float* mlp_b  = (const float*)d_in[20];
    const float* mlp_g  = (const float*)d_in[21];
    const float* mlp_be = (const float*)d_in[22];
    float* out = (float*)d_out;

    static int attr_done = 0;
    if (!attr_done) {
        cudaFuncSetAttribute(k_final_gemm_mma,
                             cudaFuncAttributeMaxDynamicSharedMemorySize, FG_SMEM);
        attr_done = 1;
    }

    for (int conv = 0; conv < 2; conv++) {
        const int* ei = conv ? geo_e : tpl_e;
        k_precompute<<<1024, 256>>>(x, prm[conv][0], prm[conv][1], conv == 0);
        k_edge_stats<<<2048, 256>>>(ei, ei + EE);
        k_edge_gemm_mma<<<296, 256>>>(ei, ei + EE, prm[conv][4], prm[conv][5],
                                      prm[conv][2], prm[conv][3]);
        k_finalize<<<1024, 256>>>(prm[conv][6], prm[conv][7], conv * HH);
    }
    k_final_gemm_mma<<<(NN + 127) / 128, 256, FG_SMEM>>>(mlp_W, mlp_b, out);
    k_norm<<<2048, 256>>>(mlp_g, mlp_be, out);
}